// round 2
// baseline (speedup 1.0000x reference)
#include <cuda_runtime.h>
#include <cstdint>

// CRF loss. Inputs: pred f32[1024,512,62], ref i32[1024,512], seq_len i32[1024],
// transitions f32[64,64]. Output: scalar f32.
//
// Forward recursion kept in LINEAR space with power-of-two rescaling:
//   u_{t+1}[j] = exp(pred[t,j]) * sum_i u_t[i] * M[i][j],  M = exp(transitions)
// renormalized each step by 2^-e (e = exponent of max w, tracked as integer).
// Rows 62/63 of M underflow to exactly 0 (transitions = -10000), so the
// start/end states drop out of the matmul automatically. Final step needs only
// column 63 (end): all_paths_b = -1000 + e_sum*ln2 + log(u_n . M[:,63]).

#define LN2F 0.69314718055994530942f

__device__ float g_Mcols[64 * 64];    // Mcols[j*64 + i] = exp(transitions[i][j]) (column-major)
__device__ float g_partials[1024];

__global__ void crf_setup(const float* __restrict__ tr) {
    int idx = blockIdx.x * blockDim.x + threadIdx.x;
    if (idx < 64 * 64) {
        int j = idx >> 6, i = idx & 63;
        g_Mcols[idx] = __expf(tr[i * 64 + j]);   // exp(-10000) -> 0 exactly
    }
}

__device__ __forceinline__ float f32x2_lo(unsigned long long v) {
    return __uint_as_float((unsigned)(v & 0xffffffffull));
}
__device__ __forceinline__ float f32x2_hi(unsigned long long v) {
    return __uint_as_float((unsigned)(v >> 32));
}

__global__ void __launch_bounds__(128) crf_forward(
    const float* __restrict__ pred, const int* __restrict__ ref,
    const int* __restrict__ seq_len, const float* __restrict__ tr)
{
    __shared__ __align__(16) float us[4][2][64];   // per-warp ping-pong u vector
    const int warp = threadIdx.x >> 5;
    const int lane = threadIdx.x & 31;
    const int b = (blockIdx.x << 2) + warp;        // grid 256 x 4 warps = 1024 batches
    const int n = seq_len[b];                      // 1..512
    const int j0 = lane;                           // column 0..31
    const int j1 = lane + 32;                      // column 32..63
    const bool has1 = (j1 < 62);                   // lanes 30,31 own start/end cols (no obs)

    const float* predb = pred + (size_t)b * (512 * 62);
    const int*   refb  = ref  + b * 512;

    // ---------------- gold (real) score ----------------
    float real = 0.f;
    for (int t = lane; t < n; t += 32) {
        int rt = refb[t];
        real += predb[t * 62 + rt];                       // emission
        int rp = (t == 0) ? 62 : refb[t - 1];             // start state = 62
        real += tr[(rp << 6) + rt];                       // transition
    }
    if (lane == 0) real += tr[(refb[n - 1] << 6) + 63];   // last -> end
    #pragma unroll
    for (int o = 16; o; o >>= 1) real += __shfl_xor_sync(0xffffffffu, real, o);

    // ---------------- M columns into registers (packed i-pairs for f32x2) ----------------
    unsigned long long M0[32], M1[32];
    {
        const unsigned long long* c0 =
            reinterpret_cast<const unsigned long long*>(g_Mcols + (j0 << 6));
        const unsigned long long* c1 =
            reinterpret_cast<const unsigned long long*>(g_Mcols + (j1 << 6));
        #pragma unroll
        for (int p = 0; p < 32; p++) { M0[p] = c0[p]; M1[p] = c1[p]; }
    }

    // ---------------- init: alpha_0 = b_s => S = -1000, u[labels]=1, u[62]=u[63]=0 ----------------
    us[warp][0][j0] = 1.0f;
    us[warp][0][j1] = has1 ? 1.0f : 0.0f;
    __syncwarp();

    float p0 = predb[j0];
    float p1 = has1 ? predb[j1] : 0.f;
    int e_sum = 0;
    int buf = 0;

    for (int t = 1; t <= n; t++) {
        // prefetch next step's observations (independent of the recursion)
        float np0 = 0.f, np1 = 0.f;
        if (t < n) {
            const float* row = predb + t * 62;
            np0 = row[j0];
            if (has1) np1 = row[j1];
        }

        // v[j] = sum_i u[i] * M[i][j]  (packed f32x2 along i; rows 62,63 of M are 0)
        unsigned long long acc0 = 0ull, acc1 = 0ull;
        const ulonglong2* ub = reinterpret_cast<const ulonglong2*>(us[warp][buf]);
        #pragma unroll
        for (int q = 0; q < 16; q++) {
            ulonglong2 uu = ub[q];   // LDS.128 broadcast (all lanes same address)
            asm("fma.rn.f32x2 %0, %1, %2, %0;" : "+l"(acc0) : "l"(M0[2 * q]),     "l"(uu.x));
            asm("fma.rn.f32x2 %0, %1, %2, %0;" : "+l"(acc1) : "l"(M1[2 * q]),     "l"(uu.x));
            asm("fma.rn.f32x2 %0, %1, %2, %0;" : "+l"(acc0) : "l"(M0[2 * q + 1]), "l"(uu.y));
            asm("fma.rn.f32x2 %0, %1, %2, %0;" : "+l"(acc1) : "l"(M1[2 * q + 1]), "l"(uu.y));
        }
        float v0 = f32x2_lo(acc0) + f32x2_hi(acc0);
        float v1 = f32x2_lo(acc1) + f32x2_hi(acc1);

        float w0 = __expf(p0) * v0;
        float w1 = has1 ? (__expf(p1) * v1) : 0.f;

        // power-of-two renormalization: w >= 0, so uint-compare == float-compare
        unsigned mm = __reduce_max_sync(0xffffffffu, __float_as_uint(fmaxf(w0, w1)));
        int ebits = (int)(mm >> 23);
        e_sum += ebits - 127;
        float inv = __uint_as_float((unsigned)(254 - ebits) << 23);   // 2^-(ebits-127)

        buf ^= 1;
        us[warp][buf][j0] = w0 * inv;
        us[warp][buf][j1] = w1 * inv;
        __syncwarp();

        p0 = np0; p1 = np1;
    }

    // ---------------- final step: only end column (63) survives ----------------
    unsigned long long accf = 0ull;
    const ulonglong2* ub = reinterpret_cast<const ulonglong2*>(us[warp][buf]);
    #pragma unroll
    for (int q = 0; q < 16; q++) {
        ulonglong2 uu = ub[q];
        asm("fma.rn.f32x2 %0, %1, %2, %0;" : "+l"(accf) : "l"(M1[2 * q]),     "l"(uu.x));
        asm("fma.rn.f32x2 %0, %1, %2, %0;" : "+l"(accf) : "l"(M1[2 * q + 1]), "l"(uu.y));
    }
    if (lane == 31) {   // lane 31's j1 == 63 == end column
        float r = f32x2_lo(accf) + f32x2_hi(accf);
        float all_paths = -1000.0f + (float)e_sum * LN2F + __logf(r);
        g_partials[b] = all_paths - real;
    }
}

__global__ void crf_reduce(float* __restrict__ out) {
    __shared__ float s[512];
    int tid = threadIdx.x;
    s[tid] = g_partials[tid] + g_partials[tid + 512];
    __syncthreads();
    #pragma unroll
    for (int o = 256; o; o >>= 1) {
        if (tid < o) s[tid] += s[tid + o];
        __syncthreads();
    }
    if (tid == 0) out[0] = s[0];
}

extern "C" void kernel_launch(void* const* d_in, const int* in_sizes, int n_in,
                              void* d_out, int out_size) {
    const float* pred = (const float*)d_in[0];
    const int*   ref  = (const int*)d_in[1];
    const int*   seq  = (const int*)d_in[2];
    const float* tr   = (const float*)d_in[3];
    float* out = (float*)d_out;

    crf_setup<<<8, 512>>>(tr);
    crf_forward<<<256, 128>>>(pred, ref, seq, tr);
    crf_reduce<<<1, 512>>>(out);
}

// round 3
// speedup vs baseline: 1.2000x; 1.2000x over previous
#include <cuda_runtime.h>
#include <cstdint>

// CRF loss. pred f32[1024,512,62], ref i32[1024,512], seq_len i32[1024],
// transitions f32[64,64] -> scalar f32.
//
// Forward recursion in LINEAR space with power-of-two rescaling every 2 steps:
//   u_{t+1}[j] = exp(pred[t,j]) * sum_i u_t[i] * M[i][j],  M = exp(transitions)
// Rows 62/63 of M are exactly 0 (transitions=-10000 -> expf underflow), so
// start/end drop out of the matvec. Final: only end column (63) survives:
//   all_paths_b = -1000 + e_sum*ln2 + log(u_n . M[:,63])

#define LN2F 0.69314718055994530942f

__device__ float g_partials[1024];

__device__ __forceinline__ float f32x2_lo(unsigned long long v) {
    return __uint_as_float((unsigned)(v & 0xffffffffull));
}
__device__ __forceinline__ float f32x2_hi(unsigned long long v) {
    return __uint_as_float((unsigned)(v >> 32));
}
__device__ __forceinline__ unsigned long long packf2(float lo, float hi) {
    return (unsigned long long)__float_as_uint(lo) |
           ((unsigned long long)__float_as_uint(hi) << 32);
}

// One recursion step. Consumes ep (=exp of obs row t-1), u in us[warp][buf].
// 3-deep obs pipeline: loads raw row t+2, exps raw row t (rA).
#define STEP_BODY(T, RENORM) do {                                              \
    float nr0 = 0.f, nr1 = 0.f;                                                \
    if ((T) + 2 < n) {                                                         \
        const float* rw = predb + ((T) + 2) * 62;                              \
        nr0 = rw[j0];                                                          \
        if (has1) nr1 = rw[j1];                                                \
    }                                                                          \
    float en0 = __expf(rA0), en1 = __expf(rA1);                                \
    unsigned long long a0 = 0ull, a0b = 0ull, a1 = 0ull, a1b = 0ull;           \
    const ulonglong2* ub = reinterpret_cast<const ulonglong2*>(us[warp][buf]); \
    _Pragma("unroll")                                                          \
    for (int q = 0; q < 16; q++) {                                             \
        ulonglong2 uu = ub[q];                                                 \
        asm("fma.rn.f32x2 %0, %1, %2, %0;" : "+l"(a0)  : "l"(M0[2*q]),   "l"(uu.x)); \
        asm("fma.rn.f32x2 %0, %1, %2, %0;" : "+l"(a1)  : "l"(M1[2*q]),   "l"(uu.x)); \
        asm("fma.rn.f32x2 %0, %1, %2, %0;" : "+l"(a0b) : "l"(M0[2*q+1]), "l"(uu.y)); \
        asm("fma.rn.f32x2 %0, %1, %2, %0;" : "+l"(a1b) : "l"(M1[2*q+1]), "l"(uu.y)); \
    }                                                                          \
    asm("add.rn.f32x2 %0, %0, %1;" : "+l"(a0) : "l"(a0b));                     \
    asm("add.rn.f32x2 %0, %0, %1;" : "+l"(a1) : "l"(a1b));                     \
    float w0 = ep0 * (f32x2_lo(a0) + f32x2_hi(a0));                            \
    float w1 = has1 ? ep1 * (f32x2_lo(a1) + f32x2_hi(a1)) : 0.f;               \
    if (RENORM) {                                                              \
        unsigned mm = __reduce_max_sync(0xffffffffu,                           \
                                        __float_as_uint(fmaxf(w0, w1)));       \
        int ebits = (int)(mm >> 23);                                           \
        e_sum += ebits - 127;                                                  \
        float inv = __uint_as_float((unsigned)(254 - ebits) << 23);            \
        w0 *= inv; w1 *= inv;                                                  \
    }                                                                          \
    buf ^= 1;                                                                  \
    us[warp][buf][j0] = w0;                                                    \
    us[warp][buf][j1] = w1;                                                    \
    __syncwarp();                                                              \
    ep0 = en0; ep1 = en1;                                                      \
    rA0 = rB0; rA1 = rB1;                                                      \
    rB0 = nr0; rB1 = nr1;                                                      \
} while (0)

__global__ void __launch_bounds__(128) crf_forward(
    const float* __restrict__ pred, const int* __restrict__ ref,
    const int* __restrict__ seq_len, const float* __restrict__ tr)
{
    __shared__ __align__(16) float us[4][2][64];
    const int warp = threadIdx.x >> 5;
    const int lane = threadIdx.x & 31;
    const int b = (blockIdx.x << 2) + warp;
    const int n = seq_len[b];                 // 1..512
    const int j0 = lane;
    const int j1 = lane + 32;
    const bool has1 = (j1 < 62);

    const float* predb = pred + (size_t)b * (512 * 62);
    const int*   refb  = ref  + b * 512;

    // ---------------- gold (real) score ----------------
    float real = 0.f;
    for (int t = lane; t < n; t += 32) {
        int rt = refb[t];
        real += predb[t * 62 + rt];
        int rp = (t == 0) ? 62 : refb[t - 1];
        real += tr[(rp << 6) + rt];
    }
    if (lane == 0) real += tr[(refb[n - 1] << 6) + 63];
    #pragma unroll
    for (int o = 16; o; o >>= 1) real += __shfl_xor_sync(0xffffffffu, real, o);

    // ---------------- build M columns in registers (packed i-pairs) ----------------
    unsigned long long M0[32], M1[32];
    #pragma unroll
    for (int p = 0; p < 32; p++) {
        float a0 = __expf(tr[(2 * p) * 64 + j0]);       // expf(-10000) -> 0
        float a1 = __expf(tr[(2 * p + 1) * 64 + j0]);
        float c0 = __expf(tr[(2 * p) * 64 + j1]);
        float c1 = __expf(tr[(2 * p + 1) * 64 + j1]);
        M0[p] = packf2(a0, a1);
        M1[p] = packf2(c0, c1);
    }

    // ---------------- init: u[labels]=1, u[62]=u[63]=0, S = -1000 ----------------
    us[warp][0][j0] = 1.0f;
    us[warp][0][j1] = has1 ? 1.0f : 0.0f;
    __syncwarp();

    // obs pipeline: ep = exp(row 0); rA = raw row 1; rB = raw row 2
    float ep0 = __expf(predb[j0]);
    float ep1 = has1 ? __expf(predb[j1]) : 1.f;
    float rA0 = 0.f, rA1 = 0.f, rB0 = 0.f, rB1 = 0.f;
    if (n >= 2) { rA0 = predb[62 + j0]; if (has1) rA1 = predb[62 + j1]; }
    if (n >= 3) { rB0 = predb[124 + j0]; if (has1) rB1 = predb[124 + j1]; }

    int e_sum = 0;
    int buf = 0;

    int t = 1;
    for (; t + 1 <= n; t += 2) {
        STEP_BODY(t, false);
        STEP_BODY(t + 1, true);
    }
    if (t == n) {
        STEP_BODY(t, false);
    }

    // ---------------- final: dot with end column M[:,63] ----------------
    unsigned long long accf = 0ull, accf2 = 0ull;
    const ulonglong2* ub = reinterpret_cast<const ulonglong2*>(us[warp][buf]);
    #pragma unroll
    for (int q = 0; q < 16; q++) {
        ulonglong2 uu = ub[q];
        asm("fma.rn.f32x2 %0, %1, %2, %0;" : "+l"(accf)  : "l"(M1[2*q]),   "l"(uu.x));
        asm("fma.rn.f32x2 %0, %1, %2, %0;" : "+l"(accf2) : "l"(M1[2*q+1]), "l"(uu.y));
    }
    asm("add.rn.f32x2 %0, %0, %1;" : "+l"(accf) : "l"(accf2));
    if (lane == 31) {                    // lane 31's j1 == 63 == end column
        float r = f32x2_lo(accf) + f32x2_hi(accf);
        float all_paths = -1000.0f + (float)e_sum * LN2F + __logf(r);
        g_partials[b] = all_paths - real;
    }
}

__global__ void crf_reduce(float* __restrict__ out) {
    __shared__ float s[512];
    int tid = threadIdx.x;
    s[tid] = g_partials[tid] + g_partials[tid + 512];
    __syncthreads();
    #pragma unroll
    for (int o = 256; o; o >>= 1) {
        if (tid < o) s[tid] += s[tid + o];
        __syncthreads();
    }
    if (tid == 0) out[0] = s[0];
}

extern "C" void kernel_launch(void* const* d_in, const int* in_sizes, int n_in,
                              void* d_out, int out_size) {
    const float* pred = (const float*)d_in[0];
    const int*   ref  = (const int*)d_in[1];
    const int*   seq  = (const int*)d_in[2];
    const float* tr   = (const float*)d_in[3];
    float* out = (float*)d_out;

    crf_forward<<<256, 128>>>(pred, ref, seq, tr);
    crf_reduce<<<1, 512>>>(out);
}